// round 15
// baseline (speedup 1.0000x reference)
#include <cuda_runtime.h>
#include <cuda_fp16.h>
#include <cuda_bf16.h>
#include <cstdint>
#include <math.h>

#define BB 4
#define TT 4096
#define EE 1024
#define DH 128
#define NHASH 8
#define NBKT 64
#define BHN 32
#define NCHUNK 512
#define SCALE 0.08838834764831845f
#define SELF_VAL (-5.0e4f)

// ---------- scratch ----------
__device__ float          g_qk[(size_t)BB * TT * EE];
__device__ float          g_v [(size_t)BB * TT * EE];
__device__ float          g_invn[(size_t)BHN * TT];
__device__ unsigned short g_bucket[(size_t)BHN * NHASH * TT];
__device__ int            g_sorted[(size_t)BHN * NHASH * TT];
__device__ float          g_ohash[(size_t)BHN * NHASH * TT * DH];
__device__ float          g_lhash[(size_t)BHN * NHASH * TT];
__device__ uint4          g_pq[(size_t)BHN * TT * 32];
__device__ uint4          g_pk[(size_t)BHN * TT * 32];
__device__ uint4          g_pvh[(size_t)BHN * TT * 16];
__device__ uint4          g_pvl[(size_t)BHN * TT * 16];
__device__ uint4          g_pattn[(size_t)BB * TT * 256];
__device__ uint4          g_pw[(size_t)EE * 256];

// ---------- fp32 SGEMM, double-buffered (bit-stable path for qk) ----------
// dyn smem: 2 stages x (sA 1024 f4 + sB 1024 f4) = 65536 B
#define SG_SMEM 65536
__global__ __launch_bounds__(256, 2)
void sgemm_abt(const float* __restrict__ A, const float* __restrict__ Bm,
               const float* __restrict__ bias, float* __restrict__ C,
               int M, int N, int K)
{
    extern __shared__ float4 smemf4[];
    int tid = threadIdx.x;
    int tx = tid & 15, ty = tid >> 4;
    int mBase = blockIdx.y * 128, nBase = blockIdx.x * 128;
    int nch = K / 32;

    float acc[8][8];
#pragma unroll
    for (int r = 0; r < 8; r++)
#pragma unroll
        for (int c = 0; c < 8; c++) acc[r][c] = 0.f;

    int ldRow = tid >> 3;          // row advance by 32 per i
    int ldF   = tid & 7;
    int swz   = ldF ^ ((ldRow >> 3) & 7);   // (row>>3)&7 constant across i? NO: row=ldRow+i*32 -> (row>>3)&7 changes with i.

    const float* Ap = A + (size_t)(mBase + ldRow) * K + ldF * 4;
    const float* Bp = Bm + (size_t)(nBase + ldRow) * K + ldF * 4;

    float4 ra[4], rb[4];
#pragma unroll
    for (int i = 0; i < 4; i++) {
        ra[i] = *(const float4*)(Ap + (size_t)(i * 32) * K);
        rb[i] = *(const float4*)(Bp + (size_t)(i * 32) * K);
    }

#define SG_STORE(buf)                                                              \
    do {                                                                           \
        float4* sA_ = smemf4 + (size_t)(buf) * 2048;                               \
        float4* sB_ = sA_ + 1024;                                                  \
        _Pragma("unroll")                                                          \
        for (int i = 0; i < 4; i++) {                                              \
            int row = ldRow + i * 32;                                              \
            sA_[row * 8 + ldF] = ra[i];                                            \
            sB_[row * 8 + (ldF ^ ((row >> 3) & 7))] = rb[i];                       \
        }                                                                          \
    } while (0)

    SG_STORE(0);
    if (nch > 1) {
        Ap += 32; Bp += 32;
#pragma unroll
        for (int i = 0; i < 4; i++) {
            ra[i] = *(const float4*)(Ap + (size_t)(i * 32) * K);
            rb[i] = *(const float4*)(Bp + (size_t)(i * 32) * K);
        }
    }
    __syncthreads();

    for (int c = 0; c < nch; c++) {
        float4* sA = smemf4 + (size_t)(c & 1) * 2048;
        float4* sB = sA + 1024;
        // issue next-next chunk's global loads early (latency hidden by compute)
        if (c + 2 < nch) { Ap += 32; Bp += 32; }
#pragma unroll
        for (int k4 = 0; k4 < 8; k4++) {
            float4 bf[8], af[8];
#pragma unroll
            for (int cc = 0; cc < 8; cc++)
                bf[cc] = sB[(tx * 8 + cc) * 8 + (k4 ^ (tx & 7))];
#pragma unroll
            for (int r = 0; r < 8; r++)
                af[r] = sA[(ty * 8 + r) * 8 + k4];
#pragma unroll
            for (int r = 0; r < 8; r++)
#pragma unroll
                for (int cc = 0; cc < 8; cc++) {
                    acc[r][cc] = fmaf(af[r].x, bf[cc].x, acc[r][cc]);
                    acc[r][cc] = fmaf(af[r].y, bf[cc].y, acc[r][cc]);
                    acc[r][cc] = fmaf(af[r].z, bf[cc].z, acc[r][cc]);
                    acc[r][cc] = fmaf(af[r].w, bf[cc].w, acc[r][cc]);
                }
        }
        if (c + 1 < nch) {
            SG_STORE((c + 1) & 1);
            if (c + 2 < nch) {
#pragma unroll
                for (int i = 0; i < 4; i++) {
                    ra[i] = *(const float4*)(Ap + (size_t)(i * 32) * K);
                    rb[i] = *(const float4*)(Bp + (size_t)(i * 32) * K);
                }
            }
        }
        __syncthreads();
    }
#undef SG_STORE

#pragma unroll
    for (int r = 0; r < 8; r++) {
        float* cp = C + (size_t)(mBase + ty * 8 + r) * N + nBase + tx * 8;
        *(float4*)cp     = make_float4(acc[r][0], acc[r][1], acc[r][2], acc[r][3]);
        *(float4*)(cp+4) = make_float4(acc[r][4], acc[r][5], acc[r][6], acc[r][7]);
    }
}

// ---------- f16 split helpers ----------
__device__ __forceinline__ void cvt_pair(float v0, float v1, unsigned& hi, unsigned& lo) {
    __half h0 = __float2half_rn(v0), h1 = __float2half_rn(v1);
    __half l0 = __float2half_rn(v0 - __half2float(h0));
    __half l1 = __float2half_rn(v1 - __half2float(h1));
    hi = ((unsigned)__half_as_ushort(h1) << 16) | (unsigned)__half_as_ushort(h0);
    lo = ((unsigned)__half_as_ushort(l1) << 16) | (unsigned)__half_as_ushort(l0);
}
__device__ __forceinline__ void mma_f16(float* d,
    unsigned a0, unsigned a1, unsigned a2, unsigned a3,
    unsigned b0, unsigned b1)
{
    asm volatile(
        "mma.sync.aligned.m16n8k16.row.col.f32.f16.f16.f32 "
        "{%0,%1,%2,%3}, {%4,%5,%6,%7}, {%8,%9}, {%0,%1,%2,%3};"
        : "+f"(d[0]), "+f"(d[1]), "+f"(d[2]), "+f"(d[3])
        : "r"(a0), "r"(a1), "r"(a2), "r"(a3), "r"(b0), "r"(b1));
}
__device__ __forceinline__ uint32_t smem_u32(const void* p) {
    uint32_t a;
    asm("{ .reg .u64 t; cvta.to.shared.u64 t, %1; cvt.u32.u64 %0, t; }" : "=r"(a) : "l"(p));
    return a;
}
#define CP_ASYNC16(dst, src) \
    asm volatile("cp.async.cg.shared.global [%0], [%1], 16;" :: "r"(dst), "l"(src) : "memory")

// ---------- f16x3 GEMM (double-buffered, cvt-in-kernel; v-proj, hidden) ----------
#define F16_ROWU4 12
#define F16_STAGE_U4 (2 * 128 * F16_ROWU4)
#define F16_SMEM2 (2 * F16_STAGE_U4 * 16)
__global__ __launch_bounds__(256, 1)
void gemm_f16x3(const float* __restrict__ A, const float* __restrict__ W,
                const float* __restrict__ bias, float* __restrict__ C,
                int K, int N)
{
    extern __shared__ char sm[];
    int tid = threadIdx.x;
    int lane = tid & 31, wid = tid >> 5;
    int wm = wid >> 2, wn = wid & 3;
    int g = lane >> 2, tig = lane & 3;
    int mBase = blockIdx.y * 128, nBase = blockIdx.x * 128;

    float acc[4][4][4];
#pragma unroll
    for (int mt = 0; mt < 4; mt++)
#pragma unroll
        for (int nt = 0; nt < 4; nt++)
#pragma unroll
            for (int r = 0; r < 4; r++) acc[mt][nt][r] = 0.f;

    int ldRow = tid >> 3;
    int ldF4  = tid & 7;
    int b_ld  = ldF4 >> 2;
    int hf    = (ldF4 >> 1) & 1;
    int tigb  = (ldF4 & 1) * 2;
    int eOff0 = (ldRow * F16_ROWU4 + b_ld * 4 + tigb) * 16 + hf * 8;
    int eOff1 = (ldRow * F16_ROWU4 + b_ld * 4 + tigb + 1) * 16 + hf * 8;

    const float* Ap = A + (size_t)(mBase + ldRow) * K + ldF4 * 4;
    const float* Wp = W + (size_t)(nBase + ldRow) * K + ldF4 * 4;
    int nch = K / 32;

    float4 ra[4], rb[4];
#pragma unroll
    for (int i = 0; i < 4; i++) {
        ra[i] = *(const float4*)(Ap + (size_t)(i * 32) * K);
        rb[i] = *(const float4*)(Wp + (size_t)(i * 32) * K);
    }

#define STORE_STAGE(stagebase)                                                     \
    do {                                                                           \
        char* sAb = (stagebase);                                                   \
        char* sBb = (stagebase) + 128 * F16_ROWU4 * 16;                            \
        _Pragma("unroll")                                                          \
        for (int i = 0; i < 4; i++) {                                              \
            unsigned hi0, lo0, hi1, lo1;                                           \
            int ro = i * 32 * F16_ROWU4 * 16;                                      \
            cvt_pair(ra[i].x, ra[i].y, hi0, lo0);                                  \
            cvt_pair(ra[i].z, ra[i].w, hi1, lo1);                                  \
            *(uint2*)(sAb + ro + eOff0) = make_uint2(hi0, lo0);                    \
            *(uint2*)(sAb + ro + eOff1) = make_uint2(hi1, lo1);                    \
            cvt_pair(rb[i].x, rb[i].y, hi0, lo0);                                  \
            cvt_pair(rb[i].z, rb[i].w, hi1, lo1);                                  \
            *(uint2*)(sBb + ro + eOff0) = make_uint2(hi0, lo0);                    \
            *(uint2*)(sBb + ro + eOff1) = make_uint2(hi1, lo1);                    \
        }                                                                          \
    } while (0)

    STORE_STAGE(sm);
    if (nch > 1) {
        Ap += 32; Wp += 32;
#pragma unroll
        for (int i = 0; i < 4; i++) {
            ra[i] = *(const float4*)(Ap + (size_t)(i * 32) * K);
            rb[i] = *(const float4*)(Wp + (size_t)(i * 32) * K);
        }
    }
    __syncthreads();

    for (int c = 0; c < nch; c++) {
        char* cur = sm + (size_t)(c & 1) * F16_STAGE_U4 * 16;
        if (c + 1 < nch) {
            char* nxt = sm + (size_t)((c + 1) & 1) * F16_STAGE_U4 * 16;
            STORE_STAGE(nxt);
        }
        if (c + 2 < nch) {
            Ap += 32; Wp += 32;
#pragma unroll
            for (int i = 0; i < 4; i++) {
                ra[i] = *(const float4*)(Ap + (size_t)(i * 32) * K);
                rb[i] = *(const float4*)(Wp + (size_t)(i * 32) * K);
            }
        }
        uint4* sA = (uint4*)cur;
        uint4* sB = sA + 128 * F16_ROWU4;
#pragma unroll
        for (int b = 0; b < 2; b++) {
            uint4 aLo[4], aHi[4], bF[4];
#pragma unroll
            for (int mt = 0; mt < 4; mt++) {
                int m = wm * 64 + mt * 16 + g;
                aLo[mt] = sA[m * F16_ROWU4 + b * 4 + tig];
                aHi[mt] = sA[(m + 8) * F16_ROWU4 + b * 4 + tig];
            }
#pragma unroll
            for (int nt = 0; nt < 4; nt++) {
                int n = wn * 32 + nt * 8 + g;
                bF[nt] = sB[n * F16_ROWU4 + b * 4 + tig];
            }
#pragma unroll
            for (int mt = 0; mt < 4; mt++)
#pragma unroll
                for (int nt = 0; nt < 4; nt++) {
                    mma_f16(acc[mt][nt], aLo[mt].x, aHi[mt].x, aLo[mt].z, aHi[mt].z,
                            bF[nt].x, bF[nt].z);
                    mma_f16(acc[mt][nt], aLo[mt].y, aHi[mt].y, aLo[mt].w, aHi[mt].w,
                            bF[nt].x, bF[nt].z);
                    mma_f16(acc[mt][nt], aLo[mt].x, aHi[mt].x, aLo[mt].z, aHi[mt].z,
                            bF[nt].y, bF[nt].w);
                }
        }
        __syncthreads();
    }
#undef STORE_STAGE

#pragma unroll
    for (int nt = 0; nt < 4; nt++) {
        int col = nBase + wn * 32 + nt * 8 + 2 * tig;
        float b0 = bias ? bias[col] : 0.f;
        float b1 = bias ? bias[col + 1] : 0.f;
#pragma unroll
        for (int mt = 0; mt < 4; mt++) {
            int row = mBase + wm * 64 + mt * 16 + g;
            *(float2*)(C + (size_t)row * N + col) =
                make_float2(acc[mt][nt][0] + b0, acc[mt][nt][1] + b1);
            *(float2*)(C + (size_t)(row + 8) * N + col) =
                make_float2(acc[mt][nt][2] + b0, acc[mt][nt][3] + b1);
        }
    }
}

// ---------- f16x3 GEMM consuming pre-packed A/W ----------
__global__ __launch_bounds__(256, 1)
void gemm_f16x3p(const uint4* __restrict__ pA, const uint4* __restrict__ pW,
                 const float* __restrict__ bias, float* __restrict__ C,
                 int K, int N)
{
    extern __shared__ char sm[];
    int tid = threadIdx.x;
    int lane = tid & 31, wid = tid >> 5;
    int wm = wid >> 2, wn = wid & 3;
    int g = lane >> 2, tig = lane & 3;
    int mBase = blockIdx.y * 128, nBase = blockIdx.x * 128;
    int K4 = K / 4;
    int nch = K / 32;
    uint32_t smb = smem_u32(sm);

    float acc[4][4][4];
#pragma unroll
    for (int mt = 0; mt < 4; mt++)
#pragma unroll
        for (int nt = 0; nt < 4; nt++)
#pragma unroll
            for (int r = 0; r < 4; r++) acc[mt][nt][r] = 0.f;

#define ISSUE_STAGE(cc, buf)                                                          \
    do {                                                                              \
        uint32_t sAa = smb + (buf) * (F16_STAGE_U4 * 16);                             \
        uint32_t sBa = sAa + 128 * F16_ROWU4 * 16;                                    \
        for (int idx = tid; idx < 1024; idx += 256) {                                 \
            int row = idx >> 3, j = idx & 7;                                          \
            CP_ASYNC16(sAa + (row * F16_ROWU4 + j) * 16,                              \
                       pA + (size_t)(mBase + row) * K4 + (cc) * 8 + j);               \
            CP_ASYNC16(sBa + (row * F16_ROWU4 + j) * 16,                              \
                       pW + (size_t)(nBase + row) * K4 + (cc) * 8 + j);               \
        }                                                                             \
        asm volatile("cp.async.commit_group;" ::: "memory");                          \
    } while (0)

    ISSUE_STAGE(0, 0);
    ISSUE_STAGE(1, 1);

    for (int c = 0; c < nch; c++) {
        asm volatile("cp.async.wait_group 1;" ::: "memory");
        __syncthreads();
        uint4* sA = (uint4*)(sm + (size_t)(c & 1) * (F16_STAGE_U4 * 16));
        uint4* sB = sA + 128 * F16_ROWU4;
#pragma unroll
        for (int b = 0; b < 2; b++) {
            uint4 aLo[4], aHi[4], bF[4];
#pragma unroll
            for (int mt = 0; mt < 4; mt++) {
                int m = wm * 64 + mt * 16 + g;
                aLo[mt] = sA[m * F16_ROWU4 + b * 4 + tig];
                aHi[mt] = sA[(m + 8) * F16_ROWU4 + b * 4 + tig];
            }
#pragma unroll
            for (int nt = 0; nt < 4; nt++) {
                int n = wn * 32 + nt * 8 + g;
                bF[nt] = sB[n * F16_ROWU4 + b * 4 + tig];
            }
#pragma unroll
            for (int mt = 0; mt < 4; mt++)
#pragma unroll
                for (int nt = 0; nt < 4; nt++) {
                    mma_f16(acc[mt][nt], aLo[mt].x, aHi[mt].x, aLo[mt].z, aHi[mt].z,
                            bF[nt].x, bF[nt].z);
                    mma_f16(acc[mt][nt], aLo[mt].y, aHi[mt].y, aLo[mt].w, aHi[mt].w,
                            bF[nt].x, bF[nt].z);
                    mma_f16(acc[mt][nt], aLo[mt].x, aHi[mt].x, aLo[mt].z, aHi[mt].z,
                            bF[nt].y, bF[nt].w);
                }
        }
        __syncthreads();
        if (c + 2 < nch) ISSUE_STAGE(c + 2, c & 1);
    }
#undef ISSUE_STAGE

#pragma unroll
    for (int nt = 0; nt < 4; nt++) {
        int col = nBase + wn * 32 + nt * 8 + 2 * tig;
        float b0 = bias ? bias[col] : 0.f;
        float b1 = bias ? bias[col + 1] : 0.f;
#pragma unroll
        for (int mt = 0; mt < 4; mt++) {
            int row = mBase + wm * 64 + mt * 16 + g;
            *(float2*)(C + (size_t)row * N + col) =
                make_float2(acc[mt][nt][0] + b0, acc[mt][nt][1] + b1);
            *(float2*)(C + (size_t)(row + 8) * N + col) =
                make_float2(acc[mt][nt][2] + b0, acc[mt][nt][3] + b1);
        }
    }
}

// ---------- pack a f32 matrix into fragment uint4s ----------
__global__ __launch_bounds__(256)
void pack_w_kernel(const float* __restrict__ W, uint4* __restrict__ dst, int K)
{
    size_t idx = (size_t)blockIdx.x * 256 + threadIdx.x;
    int K4 = K / 4;
    int row = (int)(idx / K4), l = (int)(idx % K4);
    int kb = l >> 2, tg = l & 3;
    const float* p = W + (size_t)row * K + kb * 16 + tg * 2;
    float2 a = *(const float2*)p;
    float2 c = *(const float2*)(p + 8);
    unsigned h01, l01, h89, l89;
    cvt_pair(a.x, a.y, h01, l01);
    cvt_pair(c.x, c.y, h89, l89);
    dst[idx] = make_uint4(h01, l01, h89, l89);
}

// ---------- hashing + per-token inverse norms ----------
#define HTOK 16
__global__ __launch_bounds__(512)
void hash_kernel(const float* __restrict__ rot)
{
    int bh = blockIdx.y;
    int b = bh >> 3, head = bh & 7;
    int t0 = blockIdx.x * HTOK;
    int tid = threadIdx.x;
    __shared__ __align__(16) float srow[HTOK][128];

    const float* base = g_qk + ((size_t)(b * TT + t0)) * EE + head * DH;
    for (int idx = tid; idx < HTOK * 128; idx += 512) {
        int tk = idx >> 7, f = idx & 127;
        srow[tk][f] = base[(size_t)tk * EE + f];
    }
    __syncthreads();

    int wid = tid >> 5, lane = tid & 31;
    {
        int tk = wid;
        float ss = 0.f;
        for (int f = lane; f < 128; f += 32) { float q = srow[tk][f]; ss = fmaf(q, q, ss); }
        for (int o = 16; o; o >>= 1) ss += __shfl_xor_sync(~0u, ss, o);
        if (lane == 0)
            g_invn[(size_t)bh * TT + t0 + tk] = 1.f / fmaxf(sqrtf(ss), 1e-12f);
    }

    int h = wid & 7, tg8 = (wid >> 3) * 8;
    float r[8];
#pragma unroll
    for (int tk = 0; tk < 8; tk++) r[tk] = 0.f;
    const float* rp = rot + h * 32 + lane;
#pragma unroll 2
    for (int f4 = 0; f4 < 32; ++f4) {
        float rv0 = rp[(size_t)(4 * f4 + 0) * 256];
        float rv1 = rp[(size_t)(4 * f4 + 1) * 256];
        float rv2 = rp[(size_t)(4 * f4 + 2) * 256];
        float rv3 = rp[(size_t)(4 * f4 + 3) * 256];
#pragma unroll
        for (int tk = 0; tk < 8; ++tk) {
            float4 q = *(const float4*)&srow[tg8 + tk][f4 * 4];
            r[tk] = fmaf(q.x, rv0, r[tk]);
            r[tk] = fmaf(q.y, rv1, r[tk]);
            r[tk] = fmaf(q.z, rv2, r[tk]);
            r[tk] = fmaf(q.w, rv3, r[tk]);
        }
    }
    for (int tk = 0; tk < 8; ++tk) {
        float a = fabsf(r[tk]); int bi = lane; float rv = r[tk];
        for (int o = 16; o; o >>= 1) {
            float oa  = __shfl_xor_sync(~0u, a, o);
            int   ob  = __shfl_xor_sync(~0u, bi, o);
            float orv = __shfl_xor_sync(~0u, rv, o);
            if (oa > a || (oa == a && ob < bi)) { a = oa; bi = ob; rv = orv; }
        }
        if (lane == 0) {
            int idx = (rv >= 0.f) ? bi : 32 + bi;
            g_bucket[((size_t)bh * NHASH + h) * TT + (t0 + tg8 + tk)] = (unsigned short)idx;
        }
    }
}

// ---------- pack Q/K rows ----------
__global__ __launch_bounds__(256)
void pack_kernel()
{
    int bh = blockIdx.y;
    int b = bh >> 3, head = bh & 7;
    int tid = threadIdx.x;
    int t = blockIdx.x * 8 + (tid >> 5);
    int l = tid & 31;
    int bblk = l >> 2, tg = l & 3;

    const float* base = g_qk + ((size_t)(b * TT + t)) * EE + head * DH + bblk * 16 + tg * 2;
    float2 v01 = *(const float2*)base;
    float2 v89 = *(const float2*)(base + 8);
    unsigned h01, l01, h89, l89;
    cvt_pair(v01.x, v01.y, h01, l01);
    cvt_pair(v89.x, v89.y, h89, l89);
    g_pq[((size_t)bh * TT + t) * 32 + l] = make_uint4(h01, l01, h89, l89);

    float inv = g_invn[(size_t)bh * TT + t];
    cvt_pair(v01.x * inv, v01.y * inv, h01, l01);
    cvt_pair(v89.x * inv, v89.y * inv, h89, l89);
    g_pk[((size_t)bh * TT + t) * 32 + l] = make_uint4(h01, l01, h89, l89);
}

// ---------- pack V rows ----------
__global__ __launch_bounds__(256)
void pack_v_kernel()
{
    int bh = blockIdx.y;
    int b = bh >> 3, head = bh & 7;
    int tid = threadIdx.x;
    int t = blockIdx.x * 8 + (tid >> 5);
    int l = tid & 31;

    const float* base = g_v + ((size_t)(b * TT + t)) * EE + head * DH + l * 4;
    float4 v = *(const float4*)base;
    unsigned h0, l0, h1, l1;
    cvt_pair(v.x, v.y, h0, l0);
    cvt_pair(v.z, v.w, h1, l1);
    ((uint2*)g_pvh)[((size_t)bh * TT + t) * 32 + l] = make_uint2(h0, h1);
    ((uint2*)g_pvl)[((size_t)bh * TT + t) * 32 + l] = make_uint2(l0, l1);
}

// ---------- stable counting sort ----------
__global__ __launch_bounds__(64)
void sort_kernel()
{
    int gidx = blockIdx.x;
    __shared__ unsigned char ids[TT];
    __shared__ int hist[NBKT], offs[NBKT];
    int tid = threadIdx.x;
    hist[tid] = 0;
    __syncthreads();
    const unsigned short* bp = g_bucket + (size_t)gidx * TT;
    for (int t = tid; t < TT; t += 64) {
        int vv = bp[t];
        ids[t] = (unsigned char)vv;
        atomicAdd(&hist[vv], 1);
    }
    __syncthreads();
    if (tid == 0) {
        int s = 0;
        for (int k = 0; k < NBKT; k++) { offs[k] = s; s += hist[k]; }
    }
    __syncthreads();
    int base = offs[tid];
    int* outp = g_sorted + (size_t)gidx * TT;
    for (int t = 0; t < TT; t++)
        if (ids[t] == tid) outp[base++] = t;
}

// ---------- chunk-paired LSH attention (2 chunks/block, pipelined gathers) ----------
#define QROW 36
#define VROW 272
#define SQ_OFF   0
#define SK_OFF   36864
#define VHI_OFF  110592
#define VLO_OFF  145408
#define SD_OFF   180224
#define ST0_OFF  215040
#define ST1_OFF  215552
#define AT_SMEM  216064
#define AT_THREADS 512
__global__ __launch_bounds__(AT_THREADS, 1)
void attn_kernel()
{
    extern __shared__ char smc[];
    uint4* sQ = (uint4*)(smc + SQ_OFF);
    uint4* sK = (uint4*)(smc + SK_OFF);
    char*  vhi = smc + VHI_OFF;
    char*  vlo = smc + VLO_OFF;
    float* sD = (float*)(smc + SD_OFF);
    int*   sT0 = (int*)(smc + ST0_OFF);
    int*   sT1 = (int*)(smc + ST1_OFF);

    int ck0 = blockIdx.x * 2, ck1 = ck0 + 1;
    int bh = blockIdx.y;
    int h0 = ck0 >> 6, h1 = ck1 >> 6;
    int tid = threadIdx.x;
    int lane = tid & 31, wid = tid >> 5;
    int g = lane >> 2, tig = lane & 3;
    int wm = wid >> 2, wn = wid & 3;
    int m0 = wm * 16, n0 = wn * 32;

    const int* stp = g_sorted + (size_t)bh * (NHASH * TT);
    const uint4* pq = g_pq + (size_t)bh * TT * 32;
    const uint4* pk = g_pk + (size_t)bh * TT * 32;
    const uint4* pvh = g_pvh + (size_t)bh * TT * 16;
    const uint4* pvl = g_pvl + (size_t)bh * TT * 16;

    uint32_t sQa = smem_u32(sQ), sKa = smem_u32(sK);
    uint32_t vhiA0 = smem_u32(vhi), vloA0 = smem_u32(vlo);

    if (tid < 128) {
        int pc = (ck0 + NCHUNK - 1) & (NCHUNK - 1);
        sT0[tid] = (tid < 64) ? stp[ck0 * 64 + tid] : stp[pc * 64 + (tid - 64)];
    }
    __syncthreads();

    for (int idx = tid; idx < 64 * 32; idx += AT_THREADS) {
        int row = idx >> 5, j = idx & 31;
        CP_ASYNC16(sQa + (row * QROW + j) * 16, pq + (size_t)sT0[row] * 32 + j);
    }
    for (int idx = tid; idx < 128 * 32; idx += AT_THREADS) {
        int row = idx >> 5, j = idx & 31;
        CP_ASYNC16(sKa + (row * QROW + j) * 16, pk + (size_t)sT0[row] * 32 + j);
    }
    asm volatile("cp.async.commit_group;" ::: "memory");
    for (int idx = tid; idx < 128 * 16; idx += AT_THREADS) {
        int row = idx >> 4, s = idx & 15;
        CP_ASYNC16(vhiA0 + row * VROW + s * 16, pvh + (size_t)sT0[row] * 16 + s);
        CP_ASYNC16(vloA0 + row * VROW + s * 16, pvl + (size_t)sT0[row] * 16 + s);
    }
    asm volatile("cp.async.commit_group;" ::: "memory");

#define DO_QK(sTb)                                                                 \
    {                                                                              \
        float acc[4][4];                                                           \
        _Pragma("unroll")                                                          \
        for (int nt = 0; nt < 4; nt++)                                             \
            _Pragma("unroll")                                                      \
            for (int r = 0; r < 4; r++) acc[nt][r] = 0.f;                          \
        _Pragma("unroll")                                                          \
        for (int kb = 0; kb < 8; kb++) {                                           \
            uint4 aL = sQ[(m0 + g) * QROW + kb * 4 + tig];                         \
            uint4 aH = sQ[(m0 + 8 + g) * QROW + kb * 4 + tig];                     \
            _Pragma("unroll")                                                      \
            for (int nt = 0; nt < 4; nt++) {                                       \
                uint4 bF = sK[(n0 + nt * 8 + g) * QROW + kb * 4 + tig];            \
                mma_f16(acc[nt], aL.x, aH.x, aL.z, aH.z, bF.x, bF.z);              \
                mma_f16(acc[nt], aL.y, aH.y, aL.w, aH.w, bF.x, bF.z);              \
                mma_f16(acc[nt], aL.x, aH.x, aL.z, aH.z, bF.y, bF.w);              \
            }                                                                      \
        }                                                                          \
        int r0 = m0 + g, r1 = m0 + 8 + g;                                          \
        int tq0 = (sTb)[r0], tq1 = (sTb)[r1];                                      \
        _Pragma("unroll")                                                          \
        for (int nt = 0; nt < 4; nt++) {                                           \
            int col = n0 + nt * 8 + 2 * tig;                                       \
            int tk0 = (sTb)[col], tk1 = (sTb)[col + 1];                            \
            float d0 = acc[nt][0] * SCALE, d1 = acc[nt][1] * SCALE;                \
            float d2 = acc[nt][2] * SCALE, d3 = acc[nt][3] * SCALE;                \
            if (tq0 == tk0) d0 = SELF_VAL;                                         \
            if (tq0 == tk1) d1 = SELF_VAL;                                         \
            if (tq1 == tk0) d2 = SELF_VAL;                                         \
            if (tq1 == tk1) d3 = SELF_VAL;                                         \
            *(float2*)(sD + r0 * 136 + col) = make_float2(d0, d1);                 \
            *(float2*)(sD + r1 * 136 + col) = make_float2(d2, d3);                 \
        }                                                                          \
    }

#define DO_SOFTMAX(hh, sTb)                                                        \
    for (int rr = 0; rr < 4; rr++) {                                               \
        int row = wid * 4 + rr;                                                    \
        float m = -1e30f;                                                          \
        for (int j = lane; j < 128; j += 32) m = fmaxf(m, sD[row * 136 + j]);      \
        for (int o = 16; o; o >>= 1) m = fmaxf(m, __shfl_xor_sync(~0u, m, o));     \
        float s = 0.f;                                                             \
        for (int j = lane; j < 128; j += 32) {                                     \
            float e = __expf(sD[row * 136 + j] - m);                               \
            sD[row * 136 + j] = e;                                                 \
            s += e;                                                                \
        }                                                                          \
        for (int o = 16; o; o >>= 1) s += __shfl_xor_sync(~0u, s, o);              \
        float invs = 1.f / s;                                                      \
        for (int j = lane; j < 128; j += 32)                                       \
            sD[row * 136 + j] *= invs;                                             \
        if (lane == 0)                                                             \
            g_lhash[((size_t)bh * NHASH + (hh)) * TT + (sTb)[row]] = m + __logf(s);\
    }

#define DO_PV(hh, sTb)                                                             \
    {                                                                              \
        float o_[4][4];                                                            \
        _Pragma("unroll")                                                          \
        for (int nt = 0; nt < 4; nt++)                                             \
            _Pragma("unroll")                                                      \
            for (int r = 0; r < 4; r++) o_[nt][r] = 0.f;                           \
        int jrow = (lane & 15);                                                    \
        int ncl  = ((lane >> 4) & 1) * 8;                                          \
        _Pragma("unroll")                                                          \
        for (int kb = 0; kb < 8; kb++) {                                           \
            int kc = kb * 16 + 2 * tig;                                            \
            float2 p00 = *(float2*)(sD + (m0 + g) * 136 + kc);                     \
            float2 p01 = *(float2*)(sD + (m0 + g) * 136 + kc + 8);                 \
            float2 p10 = *(float2*)(sD + (m0 + 8 + g) * 136 + kc);                 \
            float2 p11 = *(float2*)(sD + (m0 + 8 + g) * 136 + kc + 8);             \
            unsigned a0h, a0l, a1h, a1l, a2h, a2l, a3h, a3l;                       \
            cvt_pair(p00.x, p00.y, a0h, a0l);                                      \
            cvt_pair(p10.x, p10.y, a1h, a1l);                                      \
            cvt_pair(p01.x, p01.y, a2h, a2l);                                      \
            cvt_pair(p11.x, p11.y, a3h, a3l);                                      \
            int jr = kb * 16 + jrow;                                               \
            _Pragma("unroll")                                                      \
            for (int ntp = 0; ntp < 2; ntp++) {                                    \
                uint32_t addrH = vhiA0 + jr * VROW + (n0 + ntp * 16 + ncl) * 2;    \
                uint32_t addrL = vloA0 + jr * VROW + (n0 + ntp * 16 + ncl) * 2;    \
                unsigned bh0, bh1, bh2, bh3, bl0, bl1, bl2, bl3;                   \
                asm volatile("ldmatrix.sync.aligned.m8n8.x4.trans.shared.b16 "     \
                             "{%0,%1,%2,%3}, [%4];"                                \
                             : "=r"(bh0), "=r"(bh1), "=r"(bh2), "=r"(bh3)          \
                             : "r"(addrH));                                        \
                asm volatile("ldmatrix.sync.aligned.m8n8.x4.trans.shared.b16 "     \
                             "{%0,%1,%2,%3}, [%4];"                                \
                             : "=r"(bl0), "=r"(bl1), "=r"(bl2), "=r"(bl3)          \
                             : "r"(addrL));                                        \
                mma_f16(o_[2 * ntp],     a0h, a1h, a2h, a3h, bh0, bh1);            \
                mma_f16(o_[2 * ntp],     a0l, a1l, a2l, a3l, bh0, bh1);            \
                mma_f16(o_[2 * ntp],     a0h, a1h, a2h, a3h, bl0, bl1);            \
                mma_f16(o_[2 * ntp + 1], a0h, a1h, a2h, a3h, bh2, bh3);            \
                mma_f16(o_[2 * ntp + 1], a0l, a1l, a2l, a3l, bh2, bh3);            \
                mma_f16(o_[2 * ntp + 1], a0h, a1h, a2h, a3h, bl2, bl3);            \
            }                                                                      \
        }                                                                          \
        int r0 = m0 + g, r1 = m0 + 8 + g;                                          \
        float* op0 = g_ohash + (((size_t)bh * NHASH + (hh)) * TT + (sTb)[r0]) * DH;\
        float* op1 = g_ohash + (((size_t)bh * NHASH + (hh)) * TT + (sTb)[r1]) * DH;\
        _Pragma("unroll")                                                          \
        for (int nt = 0; nt < 4; nt++) {                                           \
            int col = n0 + nt * 8 + 2 * tig;                                       \
            *(float2*)(op0 + col) = make_float2(o_[nt][0], o_[nt][1]);             \
            *(float2*)(op1 + col) = make_float2(o_[nt][2], o_[nt][3]);             \
        }                                                                          \
    }

    asm volatile("cp.async.wait_group 1;" ::: "memory");
    __syncthreads();
    DO_QK(sT0);
    __syncthreads();

    if (tid < 128) {
        int pc = (ck1 + NCHUNK - 1) & (NCHUNK - 1);
        sT1[tid] = (tid < 64) ? stp[ck1 * 64 + tid] : stp[pc * 64 + (tid - 64)];
    }
    __syncthreads();
    for (int idx = tid; idx < 64 * 32; idx += AT_THREADS) {
        int row = idx >> 5, j = idx & 31;
        CP_ASYNC16(sQa + (row * QROW + j) * 16, pq + (size_t)sT1[row] * 32 + j);
    }
    for (int idx = tid; idx < 128 * 32; idx += AT_THREADS) {
        int row = idx >> 5, j = idx & 31;
        CP_ASYNC16(sKa + (row * QROW + j) * 16, pk + (size_t)sT1[row] * 32 + j);
    }
    asm volatile("cp.async.commit_group;" ::: "memory");

    DO_SOFTMAX(h0, sT0);
    asm volatile("cp.async.wait_group 1;" ::: "memory");
    __syncthreads();

    DO_PV(h0, sT0);
    __syncthreads();

    for (int idx = tid; idx < 128 * 16; idx += AT_THREADS) {
        int row = idx >> 4, s = idx & 15;
        CP_ASYNC16(vhiA0 + row * VROW + s * 16, pvh + (size_t)sT1[row] * 16 + s);
        CP_ASYNC16(vloA0 + row * VROW + s * 16, pvl + (size_t)sT1[row] * 16 + s);
    }
    asm volatile("cp.async.commit_group;" ::: "memory");

    asm volatile("cp.async.wait_group 1;" ::: "memory");
    __syncthreads();
    DO_QK(sT1);
    __syncthreads();

    DO_SOFTMAX(h1, sT1);
    asm volatile("cp.async.wait_group 0;" ::: "memory");
    __syncthreads();

    DO_PV(h1, sT1);

#undef DO_QK
#undef DO_SOFTMAX
#undef DO_PV
}

// ---------- combine hash rounds -> packed attn rows ----------
__global__ __launch_bounds__(128)
void combine_kernel()
{
    int t = blockIdx.x, bh = blockIdx.y;
    int b = bh >> 3, head = bh & 7;
    int tid = threadIdx.x;
    __shared__ float l[NHASH];
    __shared__ float co[128];
    if (tid < NHASH) l[tid] = g_lhash[((size_t)bh * NHASH + tid) * TT + t];
    __syncthreads();
    float m = -1e30f;
#pragma unroll
    for (int hh = 0; hh < NHASH; hh++) m = fmaxf(m, l[hh]);
    float s = 0.f;
#pragma unroll
    for (int hh = 0; hh < NHASH; hh++) s += expf(l[hh] - m);
    float inv = 1.f / s;
    float acc = 0.f;
#pragma unroll
    for (int hh = 0; hh < NHASH; hh++) {
        float wgt = expf(l[hh] - m) * inv;
        acc = fmaf(g_ohash[(((size_t)bh * NHASH + hh) * TT + t) * DH + tid], wgt, acc);
    }
    co[tid] = acc;
    __syncthreads();
    if (tid < 32) {
        int kb = tid >> 2, tg = tid & 3;
        unsigned h01, l01, h89, l89;
        cvt_pair(co[kb * 16 + 2 * tg], co[kb * 16 + 2 * tg + 1], h01, l01);
        cvt_pair(co[kb * 16 + 8 + 2 * tg], co[kb * 16 + 9 + 2 * tg], h89, l89);
        g_pattn[((size_t)(b * TT + t)) * 256 + head * 32 + tid] =
            make_uint4(h01, l01, h89, l89);
    }
}

// ---------- launch ----------
extern "C" void kernel_launch(void* const* d_in, const int* in_sizes, int n_in,
                              void* d_out, int out_size)
{
    const float* x     = (const float*)d_in[0];
    const float* w_qk  = (const float*)d_in[1];
    const float* w_v   = (const float*)d_in[2];
    const float* w_out = (const float*)d_in[3];
    const float* b_out = (const float*)d_in[4];
    const float* rot   = (const float*)d_in[5];
    float* out = (float*)d_out;

    float *p_qk, *p_v;
    uint4 *p_pattn, *p_pw;
    cudaGetSymbolAddress((void**)&p_qk,    g_qk);
    cudaGetSymbolAddress((void**)&p_v,     g_v);
    cudaGetSymbolAddress((void**)&p_pattn, g_pattn);
    cudaGetSymbolAddress((void**)&p_pw,    g_pw);
    cudaFuncSetAttribute(attn_kernel, cudaFuncAttributeMaxDynamicSharedMemorySize, AT_SMEM);
    cudaFuncSetAttribute(gemm_f16x3, cudaFuncAttributeMaxDynamicSharedMemorySize, F16_SMEM2);
    cudaFuncSetAttribute(gemm_f16x3p, cudaFuncAttributeMaxDynamicSharedMemorySize, F16_SMEM2);
    cudaFuncSetAttribute(sgemm_abt, cudaFuncAttributeMaxDynamicSharedMemorySize, SG_SMEM);

    static cudaStream_t s_v = nullptr;
    static cudaEvent_t ev_fork = nullptr, ev_v = nullptr;
    if (s_v == nullptr) {
        cudaStreamCreateWithFlags(&s_v, cudaStreamNonBlocking);
        cudaEventCreateWithFlags(&ev_fork, cudaEventDisableTiming);
        cudaEventCreateWithFlags(&ev_v, cudaEventDisableTiming);
    }

    dim3 gg(EE / 128, (BB * TT) / 128);

    cudaEventRecord(ev_fork, 0);
    cudaStreamWaitEvent(s_v, ev_fork, 0);
    pack_w_kernel<<<(EE * (EE / 4)) / 256, 256, 0, s_v>>>(w_out, p_pw, EE);
    gemm_f16x3<<<gg, 256, F16_SMEM2, s_v>>>(x, w_v, nullptr, p_v, EE, EE);
    pack_v_kernel<<<dim3(TT / 8, BHN), 256, 0, s_v>>>();
    cudaEventRecord(ev_v, s_v);

    sgemm_abt<<<gg, 256, SG_SMEM>>>(x, w_qk, nullptr, p_qk, BB * TT, EE, EE);
    hash_kernel<<<dim3(TT / HTOK, BHN), 512>>>(rot);
    pack_kernel<<<dim3(TT / 8, BHN), 256>>>();
    sort_kernel<<<BHN * NHASH, 64>>>();

    cudaStreamWaitEvent(0, ev_v, 0);
    attn_kernel<<<dim3(NCHUNK / 2, BHN), AT_THREADS, AT_SMEM>>>();
    combine_kernel<<<dim3(TT, BHN), 128>>>();
    gemm_f16x3p<<<gg, 256, F16_SMEM2>>>(p_pattn, p_pw, b_out, out, EE, EE);
}

// round 16
// speedup vs baseline: 1.0391x; 1.0391x over previous
#include <cuda_runtime.h>
#include <cuda_fp16.h>
#include <cuda_bf16.h>
#include <cstdint>
#include <math.h>

#define BB 4
#define TT 4096
#define EE 1024
#define DH 128
#define NHASH 8
#define NBKT 64
#define BHN 32
#define NCHUNK 512
#define SCALE 0.08838834764831845f
#define SELF_VAL (-5.0e4f)

// ---------- scratch ----------
__device__ float          g_qk[(size_t)BB * TT * EE];
__device__ float          g_v [(size_t)BB * TT * EE];
__device__ float          g_invn[(size_t)BHN * TT];
__device__ unsigned short g_bucket[(size_t)BHN * NHASH * TT];
__device__ int            g_sorted[(size_t)BHN * NHASH * TT];
__device__ float          g_ohash[(size_t)BHN * NHASH * TT * DH];
__device__ float          g_lhash[(size_t)BHN * NHASH * TT];
__device__ uint4          g_pq[(size_t)BHN * TT * 32];
__device__ uint4          g_pk[(size_t)BHN * TT * 32];
__device__ uint4          g_pvh[(size_t)BHN * TT * 16];
__device__ uint4          g_pvl[(size_t)BHN * TT * 16];
__device__ uint4          g_pattn[(size_t)BB * TT * 256];
__device__ uint4          g_pw[(size_t)EE * 256];

__device__ __forceinline__ uint32_t smem_u32(const void* p) {
    uint32_t a;
    asm("{ .reg .u64 t; cvta.to.shared.u64 t, %1; cvt.u32.u64 %0, t; }" : "=r"(a) : "l"(p));
    return a;
}
#define CP_ASYNC16(dst, src) \
    asm volatile("cp.async.cg.shared.global [%0], [%1], 16;" :: "r"(dst), "l"(src) : "memory")

// ---------- fp32 SGEMM, cp.async double-buffered (bit-stable path for qk) ----------
// dyn smem: 2 stages x (sA 16KB + sB 16KB) = 65536 B
#define SG_SMEM 65536
__global__ __launch_bounds__(256, 2)
void sgemm_abt(const float* __restrict__ A, const float* __restrict__ Bm,
               const float* __restrict__ bias, float* __restrict__ C,
               int M, int N, int K)
{
    extern __shared__ float4 smemf4[];
    uint32_t smb = smem_u32(smemf4);
    int tid = threadIdx.x;
    int tx = tid & 15, ty = tid >> 4;
    int mBase = blockIdx.y * 128, nBase = blockIdx.x * 128;
    int nch = K / 32;

    float acc[8][8];
#pragma unroll
    for (int r = 0; r < 8; r++)
#pragma unroll
        for (int c = 0; c < 8; c++) acc[r][c] = 0.f;

    int ldRow = tid >> 3;      // 0..31, rows advance by 32 per i
    int ldF   = tid & 7;       // 0..7 float4 column

#define SG_ISSUE(cc, buf)                                                          \
    do {                                                                           \
        uint32_t base_ = smb + (uint32_t)(buf) * 32768u;                           \
        _Pragma("unroll")                                                          \
        for (int i = 0; i < 4; i++) {                                              \
            int row = ldRow + i * 32;                                              \
            CP_ASYNC16(base_ + (uint32_t)(row * 8 + ldF) * 16u,                    \
                       A + (size_t)(mBase + row) * K + (cc) * 32 + ldF * 4);       \
            CP_ASYNC16(base_ + 16384u +                                            \
                           (uint32_t)(row * 8 + (ldF ^ ((row >> 3) & 7))) * 16u,   \
                       Bm + (size_t)(nBase + row) * K + (cc) * 32 + ldF * 4);      \
        }                                                                          \
        asm volatile("cp.async.commit_group;" ::: "memory");                       \
    } while (0)

    SG_ISSUE(0, 0);
    if (nch > 1) SG_ISSUE(1, 1);
    else asm volatile("cp.async.commit_group;" ::: "memory");

    for (int c = 0; c < nch; c++) {
        asm volatile("cp.async.wait_group 1;" ::: "memory");
        __syncthreads();
        float4* sA = smemf4 + (size_t)(c & 1) * 2048;
        float4* sB = sA + 1024;
#pragma unroll
        for (int k4 = 0; k4 < 8; k4++) {
            float4 bf[8], af[8];
#pragma unroll
            for (int cc = 0; cc < 8; cc++)
                bf[cc] = sB[(tx * 8 + cc) * 8 + (k4 ^ (tx & 7))];
#pragma unroll
            for (int r = 0; r < 8; r++)
                af[r] = sA[(ty * 8 + r) * 8 + k4];
#pragma unroll
            for (int r = 0; r < 8; r++)
#pragma unroll
                for (int cc = 0; cc < 8; cc++) {
                    acc[r][cc] = fmaf(af[r].x, bf[cc].x, acc[r][cc]);
                    acc[r][cc] = fmaf(af[r].y, bf[cc].y, acc[r][cc]);
                    acc[r][cc] = fmaf(af[r].z, bf[cc].z, acc[r][cc]);
                    acc[r][cc] = fmaf(af[r].w, bf[cc].w, acc[r][cc]);
                }
        }
        __syncthreads();
        if (c + 2 < nch) SG_ISSUE(c + 2, c & 1);
        else asm volatile("cp.async.commit_group;" ::: "memory");
    }
#undef SG_ISSUE

#pragma unroll
    for (int r = 0; r < 8; r++) {
        float* cp = C + (size_t)(mBase + ty * 8 + r) * N + nBase + tx * 8;
        *(float4*)cp     = make_float4(acc[r][0], acc[r][1], acc[r][2], acc[r][3]);
        *(float4*)(cp+4) = make_float4(acc[r][4], acc[r][5], acc[r][6], acc[r][7]);
    }
}

// ---------- f16 split helpers ----------
__device__ __forceinline__ void cvt_pair(float v0, float v1, unsigned& hi, unsigned& lo) {
    __half h0 = __float2half_rn(v0), h1 = __float2half_rn(v1);
    __half l0 = __float2half_rn(v0 - __half2float(h0));
    __half l1 = __float2half_rn(v1 - __half2float(h1));
    hi = ((unsigned)__half_as_ushort(h1) << 16) | (unsigned)__half_as_ushort(h0);
    lo = ((unsigned)__half_as_ushort(l1) << 16) | (unsigned)__half_as_ushort(l0);
}
__device__ __forceinline__ void mma_f16(float* d,
    unsigned a0, unsigned a1, unsigned a2, unsigned a3,
    unsigned b0, unsigned b1)
{
    asm volatile(
        "mma.sync.aligned.m16n8k16.row.col.f32.f16.f16.f32 "
        "{%0,%1,%2,%3}, {%4,%5,%6,%7}, {%8,%9}, {%0,%1,%2,%3};"
        : "+f"(d[0]), "+f"(d[1]), "+f"(d[2]), "+f"(d[3])
        : "r"(a0), "r"(a1), "r"(a2), "r"(a3), "r"(b0), "r"(b1));
}

// ---------- f16x3 GEMM (double-buffered, cvt-in-kernel; v-proj, hidden) ----------
#define F16_ROWU4 12
#define F16_STAGE_U4 (2 * 128 * F16_ROWU4)
#define F16_SMEM2 (2 * F16_STAGE_U4 * 16)
__global__ __launch_bounds__(256, 1)
void gemm_f16x3(const float* __restrict__ A, const float* __restrict__ W,
                const float* __restrict__ bias, float* __restrict__ C,
                int K, int N)
{
    extern __shared__ char sm[];
    int tid = threadIdx.x;
    int lane = tid & 31, wid = tid >> 5;
    int wm = wid >> 2, wn = wid & 3;
    int g = lane >> 2, tig = lane & 3;
    int mBase = blockIdx.y * 128, nBase = blockIdx.x * 128;

    float acc[4][4][4];
#pragma unroll
    for (int mt = 0; mt < 4; mt++)
#pragma unroll
        for (int nt = 0; nt < 4; nt++)
#pragma unroll
            for (int r = 0; r < 4; r++) acc[mt][nt][r] = 0.f;

    int ldRow = tid >> 3;
    int ldF4  = tid & 7;
    int b_ld  = ldF4 >> 2;
    int hf    = (ldF4 >> 1) & 1;
    int tigb  = (ldF4 & 1) * 2;
    int eOff0 = (ldRow * F16_ROWU4 + b_ld * 4 + tigb) * 16 + hf * 8;
    int eOff1 = (ldRow * F16_ROWU4 + b_ld * 4 + tigb + 1) * 16 + hf * 8;

    const float* Ap = A + (size_t)(mBase + ldRow) * K + ldF4 * 4;
    const float* Wp = W + (size_t)(nBase + ldRow) * K + ldF4 * 4;
    int nch = K / 32;

    float4 ra[4], rb[4];
#pragma unroll
    for (int i = 0; i < 4; i++) {
        ra[i] = *(const float4*)(Ap + (size_t)(i * 32) * K);
        rb[i] = *(const float4*)(Wp + (size_t)(i * 32) * K);
    }

#define STORE_STAGE(stagebase)                                                     \
    do {                                                                           \
        char* sAb = (stagebase);                                                   \
        char* sBb = (stagebase) + 128 * F16_ROWU4 * 16;                            \
        _Pragma("unroll")                                                          \
        for (int i = 0; i < 4; i++) {                                              \
            unsigned hi0, lo0, hi1, lo1;                                           \
            int ro = i * 32 * F16_ROWU4 * 16;                                      \
            cvt_pair(ra[i].x, ra[i].y, hi0, lo0);                                  \
            cvt_pair(ra[i].z, ra[i].w, hi1, lo1);                                  \
            *(uint2*)(sAb + ro + eOff0) = make_uint2(hi0, lo0);                    \
            *(uint2*)(sAb + ro + eOff1) = make_uint2(hi1, lo1);                    \
            cvt_pair(rb[i].x, rb[i].y, hi0, lo0);                                  \
            cvt_pair(rb[i].z, rb[i].w, hi1, lo1);                                  \
            *(uint2*)(sBb + ro + eOff0) = make_uint2(hi0, lo0);                    \
            *(uint2*)(sBb + ro + eOff1) = make_uint2(hi1, lo1);                    \
        }                                                                          \
    } while (0)

    STORE_STAGE(sm);
    if (nch > 1) {
        Ap += 32; Wp += 32;
#pragma unroll
        for (int i = 0; i < 4; i++) {
            ra[i] = *(const float4*)(Ap + (size_t)(i * 32) * K);
            rb[i] = *(const float4*)(Wp + (size_t)(i * 32) * K);
        }
    }
    __syncthreads();

    for (int c = 0; c < nch; c++) {
        char* cur = sm + (size_t)(c & 1) * F16_STAGE_U4 * 16;
        if (c + 1 < nch) {
            char* nxt = sm + (size_t)((c + 1) & 1) * F16_STAGE_U4 * 16;
            STORE_STAGE(nxt);
        }
        if (c + 2 < nch) {
            Ap += 32; Wp += 32;
#pragma unroll
            for (int i = 0; i < 4; i++) {
                ra[i] = *(const float4*)(Ap + (size_t)(i * 32) * K);
                rb[i] = *(const float4*)(Wp + (size_t)(i * 32) * K);
            }
        }
        uint4* sA = (uint4*)cur;
        uint4* sB = sA + 128 * F16_ROWU4;
#pragma unroll
        for (int b = 0; b < 2; b++) {
            uint4 aLo[4], aHi[4], bF[4];
#pragma unroll
            for (int mt = 0; mt < 4; mt++) {
                int m = wm * 64 + mt * 16 + g;
                aLo[mt] = sA[m * F16_ROWU4 + b * 4 + tig];
                aHi[mt] = sA[(m + 8) * F16_ROWU4 + b * 4 + tig];
            }
#pragma unroll
            for (int nt = 0; nt < 4; nt++) {
                int n = wn * 32 + nt * 8 + g;
                bF[nt] = sB[n * F16_ROWU4 + b * 4 + tig];
            }
#pragma unroll
            for (int mt = 0; mt < 4; mt++)
#pragma unroll
                for (int nt = 0; nt < 4; nt++) {
                    mma_f16(acc[mt][nt], aLo[mt].x, aHi[mt].x, aLo[mt].z, aHi[mt].z,
                            bF[nt].x, bF[nt].z);
                    mma_f16(acc[mt][nt], aLo[mt].y, aHi[mt].y, aLo[mt].w, aHi[mt].w,
                            bF[nt].x, bF[nt].z);
                    mma_f16(acc[mt][nt], aLo[mt].x, aHi[mt].x, aLo[mt].z, aHi[mt].z,
                            bF[nt].y, bF[nt].w);
                }
        }
        __syncthreads();
    }
#undef STORE_STAGE

#pragma unroll
    for (int nt = 0; nt < 4; nt++) {
        int col = nBase + wn * 32 + nt * 8 + 2 * tig;
        float b0 = bias ? bias[col] : 0.f;
        float b1 = bias ? bias[col + 1] : 0.f;
#pragma unroll
        for (int mt = 0; mt < 4; mt++) {
            int row = mBase + wm * 64 + mt * 16 + g;
            *(float2*)(C + (size_t)row * N + col) =
                make_float2(acc[mt][nt][0] + b0, acc[mt][nt][1] + b1);
            *(float2*)(C + (size_t)(row + 8) * N + col) =
                make_float2(acc[mt][nt][2] + b0, acc[mt][nt][3] + b1);
        }
    }
}

// ---------- f16x3 GEMM consuming pre-packed A/W ----------
__global__ __launch_bounds__(256, 1)
void gemm_f16x3p(const uint4* __restrict__ pA, const uint4* __restrict__ pW,
                 const float* __restrict__ bias, float* __restrict__ C,
                 int K, int N)
{
    extern __shared__ char sm[];
    int tid = threadIdx.x;
    int lane = tid & 31, wid = tid >> 5;
    int wm = wid >> 2, wn = wid & 3;
    int g = lane >> 2, tig = lane & 3;
    int mBase = blockIdx.y * 128, nBase = blockIdx.x * 128;
    int K4 = K / 4;
    int nch = K / 32;
    uint32_t smb = smem_u32(sm);

    float acc[4][4][4];
#pragma unroll
    for (int mt = 0; mt < 4; mt++)
#pragma unroll
        for (int nt = 0; nt < 4; nt++)
#pragma unroll
            for (int r = 0; r < 4; r++) acc[mt][nt][r] = 0.f;

#define ISSUE_STAGE(cc, buf)                                                          \
    do {                                                                              \
        uint32_t sAa = smb + (buf) * (F16_STAGE_U4 * 16);                             \
        uint32_t sBa = sAa + 128 * F16_ROWU4 * 16;                                    \
        for (int idx = tid; idx < 1024; idx += 256) {                                 \
            int row = idx >> 3, j = idx & 7;                                          \
            CP_ASYNC16(sAa + (row * F16_ROWU4 + j) * 16,                              \
                       pA + (size_t)(mBase + row) * K4 + (cc) * 8 + j);               \
            CP_ASYNC16(sBa + (row * F16_ROWU4 + j) * 16,                              \
                       pW + (size_t)(nBase + row) * K4 + (cc) * 8 + j);               \
        }                                                                             \
        asm volatile("cp.async.commit_group;" ::: "memory");                          \
    } while (0)

    ISSUE_STAGE(0, 0);
    ISSUE_STAGE(1, 1);

    for (int c = 0; c < nch; c++) {
        asm volatile("cp.async.wait_group 1;" ::: "memory");
        __syncthreads();
        uint4* sA = (uint4*)(sm + (size_t)(c & 1) * (F16_STAGE_U4 * 16));
        uint4* sB = sA + 128 * F16_ROWU4;
#pragma unroll
        for (int b = 0; b < 2; b++) {
            uint4 aLo[4], aHi[4], bF[4];
#pragma unroll
            for (int mt = 0; mt < 4; mt++) {
                int m = wm * 64 + mt * 16 + g;
                aLo[mt] = sA[m * F16_ROWU4 + b * 4 + tig];
                aHi[mt] = sA[(m + 8) * F16_ROWU4 + b * 4 + tig];
            }
#pragma unroll
            for (int nt = 0; nt < 4; nt++) {
                int n = wn * 32 + nt * 8 + g;
                bF[nt] = sB[n * F16_ROWU4 + b * 4 + tig];
            }
#pragma unroll
            for (int mt = 0; mt < 4; mt++)
#pragma unroll
                for (int nt = 0; nt < 4; nt++) {
                    mma_f16(acc[mt][nt], aLo[mt].x, aHi[mt].x, aLo[mt].z, aHi[mt].z,
                            bF[nt].x, bF[nt].z);
                    mma_f16(acc[mt][nt], aLo[mt].y, aHi[mt].y, aLo[mt].w, aHi[mt].w,
                            bF[nt].x, bF[nt].z);
                    mma_f16(acc[mt][nt], aLo[mt].x, aHi[mt].x, aLo[mt].z, aHi[mt].z,
                            bF[nt].y, bF[nt].w);
                }
        }
        __syncthreads();
        if (c + 2 < nch) ISSUE_STAGE(c + 2, c & 1);
    }
#undef ISSUE_STAGE

#pragma unroll
    for (int nt = 0; nt < 4; nt++) {
        int col = nBase + wn * 32 + nt * 8 + 2 * tig;
        float b0 = bias ? bias[col] : 0.f;
        float b1 = bias ? bias[col + 1] : 0.f;
#pragma unroll
        for (int mt = 0; mt < 4; mt++) {
            int row = mBase + wm * 64 + mt * 16 + g;
            *(float2*)(C + (size_t)row * N + col) =
                make_float2(acc[mt][nt][0] + b0, acc[mt][nt][1] + b1);
            *(float2*)(C + (size_t)(row + 8) * N + col) =
                make_float2(acc[mt][nt][2] + b0, acc[mt][nt][3] + b1);
        }
    }
}

// ---------- pack a f32 matrix into fragment uint4s ----------
__global__ __launch_bounds__(256)
void pack_w_kernel(const float* __restrict__ W, uint4* __restrict__ dst, int K)
{
    size_t idx = (size_t)blockIdx.x * 256 + threadIdx.x;
    int K4 = K / 4;
    int row = (int)(idx / K4), l = (int)(idx % K4);
    int kb = l >> 2, tg = l & 3;
    const float* p = W + (size_t)row * K + kb * 16 + tg * 2;
    float2 a = *(const float2*)p;
    float2 c = *(const float2*)(p + 8);
    unsigned h01, l01, h89, l89;
    cvt_pair(a.x, a.y, h01, l01);
    cvt_pair(c.x, c.y, h89, l89);
    dst[idx] = make_uint4(h01, l01, h89, l89);
}

// ---------- hashing + per-token inverse norms ----------
#define HTOK 16
__global__ __launch_bounds__(512)
void hash_kernel(const float* __restrict__ rot)
{
    int bh = blockIdx.y;
    int b = bh >> 3, head = bh & 7;
    int t0 = blockIdx.x * HTOK;
    int tid = threadIdx.x;
    __shared__ __align__(16) float srow[HTOK][128];

    const float* base = g_qk + ((size_t)(b * TT + t0)) * EE + head * DH;
    for (int idx = tid; idx < HTOK * 128; idx += 512) {
        int tk = idx >> 7, f = idx & 127;
        srow[tk][f] = base[(size_t)tk * EE + f];
    }
    __syncthreads();

    int wid = tid >> 5, lane = tid & 31;
    {
        int tk = wid;
        float ss = 0.f;
        for (int f = lane; f < 128; f += 32) { float q = srow[tk][f]; ss = fmaf(q, q, ss); }
        for (int o = 16; o; o >>= 1) ss += __shfl_xor_sync(~0u, ss, o);
        if (lane == 0)
            g_invn[(size_t)bh * TT + t0 + tk] = 1.f / fmaxf(sqrtf(ss), 1e-12f);
    }

    int h = wid & 7, tg8 = (wid >> 3) * 8;
    float r[8];
#pragma unroll
    for (int tk = 0; tk < 8; tk++) r[tk] = 0.f;
    const float* rp = rot + h * 32 + lane;
#pragma unroll 2
    for (int f4 = 0; f4 < 32; ++f4) {
        float rv0 = rp[(size_t)(4 * f4 + 0) * 256];
        float rv1 = rp[(size_t)(4 * f4 + 1) * 256];
        float rv2 = rp[(size_t)(4 * f4 + 2) * 256];
        float rv3 = rp[(size_t)(4 * f4 + 3) * 256];
#pragma unroll
        for (int tk = 0; tk < 8; ++tk) {
            float4 q = *(const float4*)&srow[tg8 + tk][f4 * 4];
            r[tk] = fmaf(q.x, rv0, r[tk]);
            r[tk] = fmaf(q.y, rv1, r[tk]);
            r[tk] = fmaf(q.z, rv2, r[tk]);
            r[tk] = fmaf(q.w, rv3, r[tk]);
        }
    }
    for (int tk = 0; tk < 8; ++tk) {
        float a = fabsf(r[tk]); int bi = lane; float rv = r[tk];
        for (int o = 16; o; o >>= 1) {
            float oa  = __shfl_xor_sync(~0u, a, o);
            int   ob  = __shfl_xor_sync(~0u, bi, o);
            float orv = __shfl_xor_sync(~0u, rv, o);
            if (oa > a || (oa == a && ob < bi)) { a = oa; bi = ob; rv = orv; }
        }
        if (lane == 0) {
            int idx = (rv >= 0.f) ? bi : 32 + bi;
            g_bucket[((size_t)bh * NHASH + h) * TT + (t0 + tg8 + tk)] = (unsigned short)idx;
        }
    }
}

// ---------- pack Q/K rows ----------
__global__ __launch_bounds__(256)
void pack_kernel()
{
    int bh = blockIdx.y;
    int b = bh >> 3, head = bh & 7;
    int tid = threadIdx.x;
    int t = blockIdx.x * 8 + (tid >> 5);
    int l = tid & 31;
    int bblk = l >> 2, tg = l & 3;

    const float* base = g_qk + ((size_t)(b * TT + t)) * EE + head * DH + bblk * 16 + tg * 2;
    float2 v01 = *(const float2*)base;
    float2 v89 = *(const float2*)(base + 8);
    unsigned h01, l01, h89, l89;
    cvt_pair(v01.x, v01.y, h01, l01);
    cvt_pair(v89.x, v89.y, h89, l89);
    g_pq[((size_t)bh * TT + t) * 32 + l] = make_uint4(h01, l01, h89, l89);

    float inv = g_invn[(size_t)bh * TT + t];
    cvt_pair(v01.x * inv, v01.y * inv, h01, l01);
    cvt_pair(v89.x * inv, v89.y * inv, h89, l89);
    g_pk[((size_t)bh * TT + t) * 32 + l] = make_uint4(h01, l01, h89, l89);
}

// ---------- pack V rows ----------
__global__ __launch_bounds__(256)
void pack_v_kernel()
{
    int bh = blockIdx.y;
    int b = bh >> 3, head = bh & 7;
    int tid = threadIdx.x;
    int t = blockIdx.x * 8 + (tid >> 5);
    int l = tid & 31;

    const float* base = g_v + ((size_t)(b * TT + t)) * EE + head * DH + l * 4;
    float4 v = *(const float4*)base;
    unsigned h0, l0, h1, l1;
    cvt_pair(v.x, v.y, h0, l0);
    cvt_pair(v.z, v.w, h1, l1);
    ((uint2*)g_pvh)[((size_t)bh * TT + t) * 32 + l] = make_uint2(h0, h1);
    ((uint2*)g_pvl)[((size_t)bh * TT + t) * 32 + l] = make_uint2(l0, l1);
}

// ---------- stable counting sort ----------
__global__ __launch_bounds__(64)
void sort_kernel()
{
    int gidx = blockIdx.x;
    __shared__ unsigned char ids[TT];
    __shared__ int hist[NBKT], offs[NBKT];
    int tid = threadIdx.x;
    hist[tid] = 0;
    __syncthreads();
    const unsigned short* bp = g_bucket + (size_t)gidx * TT;
    for (int t = tid; t < TT; t += 64) {
        int vv = bp[t];
        ids[t] = (unsigned char)vv;
        atomicAdd(&hist[vv], 1);
    }
    __syncthreads();
    if (tid == 0) {
        int s = 0;
        for (int k = 0; k < NBKT; k++) { offs[k] = s; s += hist[k]; }
    }
    __syncthreads();
    int base = offs[tid];
    int* outp = g_sorted + (size_t)gidx * TT;
    for (int t = 0; t < TT; t++)
        if (ids[t] == tid) outp[base++] = t;
}

// ---------- chunk-paired LSH attention (2 chunks/block, pipelined gathers) ----------
#define QROW 36
#define VROW 272
#define SQ_OFF   0
#define SK_OFF   36864
#define VHI_OFF  110592
#define VLO_OFF  145408
#define SD_OFF   180224
#define ST0_OFF  215040
#define ST1_OFF  215552
#define AT_SMEM  216064
#define AT_THREADS 512
__global__ __launch_bounds__(AT_THREADS, 1)
void attn_kernel()
{
    extern __shared__ char smc[];
    uint4* sQ = (uint4*)(smc + SQ_OFF);
    uint4* sK = (uint4*)(smc + SK_OFF);
    char*  vhi = smc + VHI_OFF;
    char*  vlo = smc + VLO_OFF;
    float* sD = (float*)(smc + SD_OFF);
    int*   sT0 = (int*)(smc + ST0_OFF);
    int*   sT1 = (int*)(smc + ST1_OFF);

    int ck0 = blockIdx.x * 2, ck1 = ck0 + 1;
    int bh = blockIdx.y;
    int h0 = ck0 >> 6, h1 = ck1 >> 6;
    int tid = threadIdx.x;
    int lane = tid & 31, wid = tid >> 5;
    int g = lane >> 2, tig = lane & 3;
    int wm = wid >> 2, wn = wid & 3;
    int m0 = wm * 16, n0 = wn * 32;

    const int* stp = g_sorted + (size_t)bh * (NHASH * TT);
    const uint4* pq = g_pq + (size_t)bh * TT * 32;
    const uint4* pk = g_pk + (size_t)bh * TT * 32;
    const uint4* pvh = g_pvh + (size_t)bh * TT * 16;
    const uint4* pvl = g_pvl + (size_t)bh * TT * 16;

    uint32_t sQa = smem_u32(sQ), sKa = smem_u32(sK);
    uint32_t vhiA0 = smem_u32(vhi), vloA0 = smem_u32(vlo);

    if (tid < 128) {
        int pc = (ck0 + NCHUNK - 1) & (NCHUNK - 1);
        sT0[tid] = (tid < 64) ? stp[ck0 * 64 + tid] : stp[pc * 64 + (tid - 64)];
    }
    __syncthreads();

    for (int idx = tid; idx < 64 * 32; idx += AT_THREADS) {
        int row = idx >> 5, j = idx & 31;
        CP_ASYNC16(sQa + (row * QROW + j) * 16, pq + (size_t)sT0[row] * 32 + j);
    }
    for (int idx = tid; idx < 128 * 32; idx += AT_THREADS) {
        int row = idx >> 5, j = idx & 31;
        CP_ASYNC16(sKa + (row * QROW + j) * 16, pk + (size_t)sT0[row] * 32 + j);
    }
    asm volatile("cp.async.commit_group;" ::: "memory");
    for (int idx = tid; idx < 128 * 16; idx += AT_THREADS) {
        int row = idx >> 4, s = idx & 15;
        CP_ASYNC16(vhiA0 + row * VROW + s * 16, pvh + (size_t)sT0[row] * 16 + s);
        CP_ASYNC16(vloA0 + row * VROW + s * 16, pvl + (size_t)sT0[row] * 16 + s);
    }
    asm volatile("cp.async.commit_group;" ::: "memory");

#define DO_QK(sTb)                                                                 \
    {                                                                              \
        float acc[4][4];                                                           \
        _Pragma("unroll")                                                          \
        for (int nt = 0; nt < 4; nt++)                                             \
            _Pragma("unroll")                                                      \
            for (int r = 0; r < 4; r++) acc[nt][r] = 0.f;                          \
        _Pragma("unroll")                                                          \
        for (int kb = 0; kb < 8; kb++) {                                           \
            uint4 aL = sQ[(m0 + g) * QROW + kb * 4 + tig];                         \
            uint4 aH = sQ[(m0 + 8 + g) * QROW + kb * 4 + tig];                     \
            _Pragma("unroll")                                                      \
            for (int nt = 0; nt < 4; nt++) {                                       \
                uint4 bF = sK[(n0 + nt * 8 + g) * QROW + kb * 4 + tig];            \
                mma_f16(acc[nt], aL.x, aH.x, aL.z, aH.z, bF.x, bF.z);              \
                mma_f16(acc[nt], aL.y, aH.y, aL.w, aH.w, bF.x, bF.z);              \
                mma_f16(acc[nt], aL.x, aH.x, aL.z, aH.z, bF.y, bF.w);              \
            }                                                                      \
        }                                                                          \
        int r0 = m0 + g, r1 = m0 + 8 + g;                                          \
        int tq0 = (sTb)[r0], tq1 = (sTb)[r1];                                      \
        _Pragma("unroll")                                                          \
        for (int nt = 0; nt < 4; nt++) {                                           \
            int col = n0 + nt * 8 + 2 * tig;                                       \
            int tk0 = (sTb)[col], tk1 = (sTb)[col + 1];                            \
            float d0 = acc[nt][0] * SCALE, d1 = acc[nt][1] * SCALE;                \
            float d2 = acc[nt][2] * SCALE, d3 = acc[nt][3] * SCALE;                \
            if (tq0 == tk0) d0 = SELF_VAL;                                         \
            if (tq0 == tk1) d1 = SELF_VAL;                                         \
            if (tq1 == tk0) d2 = SELF_VAL;                                         \
            if (tq1 == tk1) d3 = SELF_VAL;                                         \
            *(float2*)(sD + r0 * 136 + col) = make_float2(d0, d1);                 \
            *(float2*)(sD + r1 * 136 + col) = make_float2(d2, d3);                 \
        }                                                                          \
    }

#define DO_SOFTMAX(hh, sTb)                                                        \
    for (int rr = 0; rr < 4; rr++) {                                               \
        int row = wid * 4 + rr;                                                    \
        float m = -1e30f;                                                          \
        for (int j = lane; j < 128; j += 32) m = fmaxf(m, sD[row * 136 + j]);      \
        for (int o = 16; o; o >>= 1) m = fmaxf(m, __shfl_xor_sync(~0u, m, o));     \
        float s = 0.f;                                                             \
        for (int j = lane; j < 128; j += 32) {                                     \
            float e = __expf(sD[row * 136 + j] - m);                               \
            sD[row * 136 + j] = e;                                                 \
            s += e;                                                                \
        }                                                                          \
        for (int o = 16; o; o >>= 1) s += __shfl_xor_sync(~0u, s, o);              \
        float invs = 1.f / s;                                                      \
        for (int j = lane; j < 128; j += 32)                                       \
            sD[row * 136 + j] *= invs;                                             \
        if (lane == 0)                                                             \
            g_lhash[((size_t)bh * NHASH + (hh)) * TT + (sTb)[row]] = m + __logf(s);\
    }

#define DO_PV(hh, sTb)                                                             \
    {                                                                              \
        float o_[4][4];                                                            \
        _Pragma("unroll")                                                          \
        for (int nt = 0; nt < 4; nt++)                                             \
            _Pragma("unroll")                                                      \
            for (int r = 0; r < 4; r++) o_[nt][r] = 0.f;                           \
        int jrow = (lane & 15);                                                    \
        int ncl  = ((lane >> 4) & 1) * 8;                                          \
        _Pragma("unroll")                                                          \
        for (int kb = 0; kb < 8; kb++) {                                           \
            int kc = kb * 16 + 2 * tig;                                            \
            float2 p00 = *(float2*)(sD + (m0 + g) * 136 + kc);                     \
            float2 p01 = *(float2*)(sD + (m0 + g) * 136 + kc + 8);                 \
            float2 p10 = *(float2*)(sD + (m0 + 8 + g) * 136 + kc);                 \
            float2 p11 = *(float2*)(sD + (m0 + 8 + g) * 136 + kc + 8);             \
            unsigned a0h, a0l, a1h, a1l, a2h, a2l, a3h, a3l;                       \
            cvt_pair(p00.x, p00.y, a0h, a0l);                                      \
            cvt_pair(p10.x, p10.y, a1h, a1l);                                      \
            cvt_pair(p01.x, p01.y, a2h, a2l);                                      \
            cvt_pair(p11.x, p11.y, a3h, a3l);                                      \
            int jr = kb * 16 + jrow;                                               \
            _Pragma("unroll")                                                      \
            for (int ntp = 0; ntp < 2; ntp++) {                                    \
                uint32_t addrH = vhiA0 + jr * VROW + (n0 + ntp * 16 + ncl) * 2;    \
                uint32_t addrL = vloA0 + jr * VROW + (n0 + ntp * 16 + ncl) * 2;    \
                unsigned bh0, bh1, bh2, bh3, bl0, bl1, bl2, bl3;                   \
                asm volatile("ldmatrix.sync.aligned.m8n8.x4.trans.shared.b16 "     \
                             "{%0,%1,%2,%3}, [%4];"                                \
                             : "=r"(bh0), "=r"(bh1), "=r"(bh2), "=r"(bh3)          \
                             : "r"(addrH));                                        \
                asm volatile("ldmatrix.sync.aligned.m8n8.x4.trans.shared.b16 "     \
                             "{%0,%1,%2,%3}, [%4];"                                \
                             : "=r"(bl0), "=r"(bl1), "=r"(bl2), "=r"(bl3)          \
                             : "r"(addrL));                                        \
                mma_f16(o_[2 * ntp],     a0h, a1h, a2h, a3h, bh0, bh1);            \
                mma_f16(o_[2 * ntp],     a0l, a1l, a2l, a3l, bh0, bh1);            \
                mma_f16(o_[2 * ntp],     a0h, a1h, a2h, a3h, bl0, bl1);            \
                mma_f16(o_[2 * ntp + 1], a0h, a1h, a2h, a3h, bh2, bh3);            \
                mma_f16(o_[2 * ntp + 1], a0l, a1l, a2l, a3l, bh2, bh3);            \
                mma_f16(o_[2 * ntp + 1], a0h, a1h, a2h, a3h, bl2, bl3);            \
            }                                                                      \
        }                                                                          \
        int r0 = m0 + g, r1 = m0 + 8 + g;                                          \
        float* op0 = g_ohash + (((size_t)bh * NHASH + (hh)) * TT + (sTb)[r0]) * DH;\
        float* op1 = g_ohash + (((size_t)bh * NHASH + (hh)) * TT + (sTb)[r1]) * DH;\
        _Pragma("unroll")                                                          \
        for (int nt = 0; nt < 4; nt++) {                                           \
            int col = n0 + nt * 8 + 2 * tig;                                       \
            *(float2*)(op0 + col) = make_float2(o_[nt][0], o_[nt][1]);             \
            *(float2*)(op1 + col) = make_float2(o_[nt][2], o_[nt][3]);             \
        }                                                                          \
    }

    asm volatile("cp.async.wait_group 1;" ::: "memory");
    __syncthreads();
    DO_QK(sT0);
    __syncthreads();

    if (tid < 128) {
        int pc = (ck1 + NCHUNK - 1) & (NCHUNK - 1);
        sT1[tid] = (tid < 64) ? stp[ck1 * 64 + tid] : stp[pc * 64 + (tid - 64)];
    }
    __syncthreads();
    for (int idx = tid; idx < 64 * 32; idx += AT_THREADS) {
        int row = idx >> 5, j = idx & 31;
        CP_ASYNC16(sQa + (row * QROW + j) * 16, pq + (size_t)sT1[row] * 32 + j);
    }
    for (int idx = tid; idx < 128 * 32; idx += AT_THREADS) {
        int row = idx >> 5, j = idx & 31;
        CP_ASYNC16(sKa + (row * QROW + j) * 16, pk + (size_t)sT1[row] * 32 + j);
    }
    asm volatile("cp.async.commit_group;" ::: "memory");

    DO_SOFTMAX(h0, sT0);
    asm volatile("cp.async.wait_group 1;" ::: "memory");
    __syncthreads();

    DO_PV(h0, sT0);
    __syncthreads();

    for (int idx = tid; idx < 128 * 16; idx += AT_THREADS) {
        int row = idx >> 4, s = idx & 15;
        CP_ASYNC16(vhiA0 + row * VROW + s * 16, pvh + (size_t)sT1[row] * 16 + s);
        CP_ASYNC16(vloA0 + row * VROW + s * 16, pvl + (size_t)sT1[row] * 16 + s);
    }
    asm volatile("cp.async.commit_group;" ::: "memory");

    asm volatile("cp.async.wait_group 1;" ::: "memory");
    __syncthreads();
    DO_QK(sT1);
    __syncthreads();

    DO_SOFTMAX(h1, sT1);
    asm volatile("cp.async.wait_group 0;" ::: "memory");
    __syncthreads();

    DO_PV(h1, sT1);

#undef DO_QK
#undef DO_SOFTMAX
#undef DO_PV
}

// ---------- combine hash rounds -> packed attn rows ----------
__global__ __launch_bounds__(128)
void combine_kernel()
{
    int t = blockIdx.x, bh = blockIdx.y;
    int b = bh >> 3, head = bh & 7;
    int tid = threadIdx.x;
    __shared__ float l[NHASH];
    __shared__ float co[128];
    if (tid < NHASH) l[tid] = g_lhash[((size_t)bh * NHASH + tid) * TT + t];
    __syncthreads();
    float m = -1e30f;
#pragma unroll
    for (int hh = 0; hh < NHASH; hh++) m = fmaxf(m, l[hh]);
    float s = 0.f;
#pragma unroll
    for (int hh = 0; hh < NHASH; hh++) s += expf(l[hh] - m);
    float inv = 1.f / s;
    float acc = 0.f;
#pragma unroll
    for (int hh = 0; hh < NHASH; hh++) {
        float wgt = expf(l[hh] - m) * inv;
        acc = fmaf(g_ohash[(((size_t)bh * NHASH + hh) * TT + t) * DH + tid], wgt, acc);
    }
    co[tid] = acc;
    __syncthreads();
    if (tid < 32) {
        int kb = tid >> 2, tg = tid & 3;
        unsigned h01, l01, h89, l89;
        cvt_pair(co[kb * 16 + 2 * tg], co[kb * 16 + 2 * tg + 1], h01, l01);
        cvt_pair(co[kb * 16 + 8 + 2 * tg], co[kb * 16 + 9 + 2 * tg], h89, l89);
        g_pattn[((size_t)(b * TT + t)) * 256 + head * 32 + tid] =
            make_uint4(h01, l01, h89, l89);
    }
}

// ---------- launch ----------
extern "C" void kernel_launch(void* const* d_in, const int* in_sizes, int n_in,
                              void* d_out, int out_size)
{
    const float* x     = (const float*)d_in[0];
    const float* w_qk  = (const float*)d_in[1];
    const float* w_v   = (const float*)d_in[2];
    const float* w_out = (const float*)d_in[3];
    const float* b_out = (const float*)d_in[4];
    const float* rot   = (const float*)d_in[5];
    float* out = (float*)d_out;

    float *p_qk, *p_v;
    uint4 *p_pattn, *p_pw;
    cudaGetSymbolAddress((void**)&p_qk,    g_qk);
    cudaGetSymbolAddress((void**)&p_v,     g_v);
    cudaGetSymbolAddress((void**)&p_pattn, g_pattn);
    cudaGetSymbolAddress((void**)&p_pw,    g_pw);
    cudaFuncSetAttribute(attn_kernel, cudaFuncAttributeMaxDynamicSharedMemorySize, AT_SMEM);
    cudaFuncSetAttribute(gemm_f16x3, cudaFuncAttributeMaxDynamicSharedMemorySize, F16_SMEM2);
    cudaFuncSetAttribute(gemm_f16x3p, cudaFuncAttributeMaxDynamicSharedMemorySize, F16_SMEM2);
    cudaFuncSetAttribute(sgemm_abt, cudaFuncAttributeMaxDynamicSharedMemorySize, SG_SMEM);

    static cudaStream_t s_v = nullptr;
    static cudaEvent_t ev_fork = nullptr, ev_v = nullptr;
    if (s_v == nullptr) {
        cudaStreamCreateWithFlags(&s_v, cudaStreamNonBlocking);
        cudaEventCreateWithFlags(&ev_fork, cudaEventDisableTiming);
        cudaEventCreateWithFlags(&ev_v, cudaEventDisableTiming);
    }

    dim3 gg(EE / 128, (BB * TT) / 128);

    cudaEventRecord(ev_fork, 0);
    cudaStreamWaitEvent(s_v, ev_fork, 0);
    pack_w_kernel<<<(EE * (EE / 4)) / 256, 256, 0, s_v>>>(w_out, p_pw, EE);
    gemm_f16x3<<<gg, 256, F16_SMEM2, s_v>>>(x, w_v, nullptr, p_v, EE, EE);
    pack_v_kernel<<<dim3(TT / 8, BHN), 256, 0, s_v>>>();
    cudaEventRecord(ev_v, s_v);

    sgemm_abt<<<gg, 256, SG_SMEM>>>(x, w_qk, nullptr, p_qk, BB * TT, EE, EE);
    hash_kernel<<<dim3(TT / HTOK, BHN), 512>>>(rot);
    pack_kernel<<<dim3(TT / 8, BHN), 256>>>();
    sort_kernel<<<BHN * NHASH, 64>>>();

    cudaStreamWaitEvent(0, ev_v, 0);
    attn_kernel<<<dim3(NCHUNK / 2, BHN), AT_THREADS, AT_SMEM>>>();
    combine_kernel<<<dim3(TT, BHN), 128>>>();
    gemm_f16x3p<<<gg, 256, F16_SMEM2>>>(p_pattn, p_pw, b_out, out, EE, EE);
}